// round 9
// baseline (speedup 1.0000x reference)
#include <cuda_runtime.h>
#include <cuda_fp16.h>
#include <cstdint>

#define N_NODES 20000
#define E_EDGES 640000
#define VOFF (N_NODES * 9)

// fragment-ordered weight tiles: [tile][hi:0..8191 | lo:8192..16383] u32 (2 fp16 each)
// tiles: 0=L0a 1=L0b 2=L1 3=Lx0 4=Lx1 5=H0a 6=H0b 7=H1 8=H2
__device__ __align__(16) uint32_t g_WF[9][16384];
__device__ float g_W0c[384];    // w_e0 rows 256..258, [v][out]
__device__ float g_Wout[384];   // phi_x_out_w^T [v][k]
__device__ __align__(16) float g_mAcc[N_NODES * 128];
__device__ __align__(16) float g_vAcc[N_NODES * 9];

// edge smem (float units): buf0 u32[8192] | buf1 u32[8192] | bias 1536 | vec 2048 | recv 128
#define EF_BIAS 16384
#define EF_VEC  17920
#define EF_RECV 19968
#define ESM_BYTES (20096 * 4)
// node smem: buf0|buf1|buf2 u32[8192 each] | bias 384
#define NF_BIAS 24576
#define NSM_BYTES (24960 * 4)

// ---------------- fast activations (MUFU ex2/rcp) ----------------
__device__ __forceinline__ float fsilu(float x) {
    float e; asm("ex2.approx.f32 %0, %1;" : "=f"(e) : "f"(x * -1.44269504f));
    float r; asm("rcp.approx.f32 %0, %1;" : "=f"(r) : "f"(1.0f + e));
    return x * r;
}
__device__ __forceinline__ float fsigmoid(float x) {
    float e; asm("ex2.approx.f32 %0, %1;" : "=f"(e) : "f"(x * -1.44269504f));
    float r; asm("rcp.approx.f32 %0, %1;" : "=f"(r) : "f"(1.0f + e));
    return r;
}
__device__ __forceinline__ float frcp(float d) {
    float r; asm("rcp.approx.f32 %0, %1;" : "=f"(r) : "f"(d));
    return r;
}

// ---------------- frag / mma helpers ----------------
__device__ __forceinline__ uint32_t smem_u32(const void* p) {
    uint32_t a;
    asm("{ .reg .u64 t; cvta.to.shared.u64 t, %1; cvt.u32.u64 %0, t; }" : "=r"(a) : "l"(p));
    return a;
}
__device__ __forceinline__ uint32_t pack2(float x, float y) {
    __half2 h = __floats2half2_rn(x, y);
    return *reinterpret_cast<uint32_t*>(&h);
}
__device__ __forceinline__ void split2(float x, float y, uint32_t& hi, uint32_t& lo) {
    __half2 h = __floats2half2_rn(x, y);
    float2 hf = __half22float2(h);
    __half2 l = __floats2half2_rn(x - hf.x, y - hf.y);
    hi = *reinterpret_cast<uint32_t*>(&h);
    lo = *reinterpret_cast<uint32_t*>(&l);
}
__device__ __forceinline__ void mma16816(float* d, const uint32_t* a, uint32_t b0, uint32_t b1) {
    asm volatile("mma.sync.aligned.m16n8k16.row.col.f32.f16.f16.f32 "
                 "{%0,%1,%2,%3}, {%4,%5,%6,%7}, {%8,%9}, {%0,%1,%2,%3};"
                 : "+f"(d[0]), "+f"(d[1]), "+f"(d[2]), "+f"(d[3])
                 : "r"(a[0]), "r"(a[1]), "r"(a[2]), "r"(a[3]), "r"(b0), "r"(b1));
}
// two fragment groups share each B load — edge kernel
__device__ __forceinline__ void mma2g(float (&dA)[16][4], float (&dB)[16][4],
                                      const uint32_t (&ahA)[8][4], const uint32_t (&ahB)[8][4],
                                      const uint32_t* swHi, int lane) {
#pragma unroll
    for (int kc = 0; kc < 8; kc++)
#pragma unroll
        for (int j = 0; j < 16; j++) {
            uint2 b = *(const uint2*)&swHi[((kc * 16 + j) * 32 + lane) * 2];
            mma16816(dA[j], ahA[kc], b.x, b.y);
            mma16816(dB[j], ahB[kc], b.x, b.y);
        }
}
// 2-pass (ah*Whi + al*Whi) — node kernel
__device__ __forceinline__ void mma12(float (&d)[16][4], const uint32_t (&ah)[8][4],
                                      const uint32_t (&al)[8][4], const uint32_t* swHi, int lane) {
#pragma unroll
    for (int kc = 0; kc < 8; kc++)
#pragma unroll
        for (int j = 0; j < 16; j++) {
            uint2 b = *(const uint2*)&swHi[((kc * 16 + j) * 32 + lane) * 2];
            mma16816(d[j], ah[kc], b.x, b.y);
            mma16816(d[j], al[kc], b.x, b.y);
        }
}
// pass 3 (ah*Wlo) — node kernel
__device__ __forceinline__ void mma3(float (&d)[16][4], const uint32_t (&ah)[8][4],
                                     const uint32_t* swLo, int lane) {
#pragma unroll
    for (int kc = 0; kc < 8; kc++)
#pragma unroll
        for (int j = 0; j < 16; j++) {
            uint2 b = *(const uint2*)&swLo[((kc * 16 + j) * 32 + lane) * 2];
            mma16816(d[j], ah[kc], b.x, b.y);
        }
}
__device__ __forceinline__ void zero_d(float (&d)[16][4]) {
#pragma unroll
    for (int j = 0; j < 16; j++)
#pragma unroll
        for (int q = 0; q < 4; q++) d[j][q] = 0.f;
}
// load one 32KB half-tile (2048 x 16B), own commit group
__device__ __forceinline__ void loadW32(uint32_t sAddr, const uint32_t* g, int tid) {
#pragma unroll 1
    for (int i = tid; i < 2048; i += 128)
        asm volatile("cp.async.cg.shared.global [%0], [%1], 16;"
                     :: "r"(sAddr + i * 16), "l"(g + i * 4));
    asm volatile("cp.async.commit_group;" ::: "memory");
}
__device__ __forceinline__ void waitW0() { asm volatile("cp.async.wait_group 0;" ::: "memory"); }
__device__ __forceinline__ void waitW1() { asm volatile("cp.async.wait_group 1;" ::: "memory"); }
__device__ __forceinline__ void red2(float* p, float x, float y) {
    asm volatile("red.global.add.v2.f32 [%0], {%1,%2};" :: "l"(p), "f"(x), "f"(y) : "memory");
}
// gather one K=16 chunk of two fp32 rows into fp16 A frags (hi only)
__device__ __forceinline__ void gfrag1(const float* f0, const float* f1, int kc, int tig,
                                       uint32_t (&ah)[8][4]) {
    float2 x0 = __ldg((const float2*)(f0 + kc * 16 + 2 * tig));
    float2 x1 = __ldg((const float2*)(f1 + kc * 16 + 2 * tig));
    float2 y0 = __ldg((const float2*)(f0 + kc * 16 + 8 + 2 * tig));
    float2 y1 = __ldg((const float2*)(f1 + kc * 16 + 8 + 2 * tig));
    ah[kc][0] = pack2(x0.x, x0.y);
    ah[kc][1] = pack2(x1.x, x1.y);
    ah[kc][2] = pack2(y0.x, y0.y);
    ah[kc][3] = pack2(y1.x, y1.y);
}
// hi/lo gather for node kernel
__device__ __forceinline__ void gfrag(const float* f0, const float* f1, int kc, int tig,
                                      uint32_t (&ah)[8][4], uint32_t (&al)[8][4],
                                      bool v0, bool v1, float scale) {
    float2 z = make_float2(0.f, 0.f);
    float2 x0 = v0 ? __ldg((const float2*)(f0 + kc * 16 + 2 * tig)) : z;
    float2 x1 = v1 ? __ldg((const float2*)(f1 + kc * 16 + 2 * tig)) : z;
    float2 y0 = v0 ? __ldg((const float2*)(f0 + kc * 16 + 8 + 2 * tig)) : z;
    float2 y1 = v1 ? __ldg((const float2*)(f1 + kc * 16 + 8 + 2 * tig)) : z;
    split2(x0.x * scale, x0.y * scale, ah[kc][0], al[kc][0]);
    split2(x1.x * scale, x1.y * scale, ah[kc][1], al[kc][1]);
    split2(y0.x * scale, y0.y * scale, ah[kc][2], al[kc][2]);
    split2(y1.x * scale, y1.y * scale, ah[kc][3], al[kc][3]);
}
// plain bias+silu epilogue -> fp16 frags
__device__ __forceinline__ void epi_silu(float (&d)[16][4], const float* bias, int tig,
                                         uint32_t (&ah)[8][4]) {
#pragma unroll
    for (int kc = 0; kc < 8; kc++)
#pragma unroll
        for (int u = 0; u < 2; u++) {
            int j = 2 * kc + u, c = j * 8 + 2 * tig;
            float2 bb = *(const float2*)(bias + c);
            float v0 = fsilu(d[j][0] + bb.x), v1 = fsilu(d[j][1] + bb.y);
            float v2 = fsilu(d[j][2] + bb.x), v3 = fsilu(d[j][3] + bb.y);
            ah[kc][2 * u]     = pack2(v0, v1);
            ah[kc][2 * u + 1] = pack2(v2, v3);
        }
}
// L0 epilogue: + bias + sq·w0c, silu -> frags
__device__ __forceinline__ void epi_l0(float (&d)[16][4], const float* sBias, int tig,
                                       float sa0, float sa1, float sa2,
                                       float sb0, float sb1, float sb2,
                                       uint32_t (&ah)[8][4]) {
#pragma unroll
    for (int kc = 0; kc < 8; kc++)
#pragma unroll
        for (int u = 0; u < 2; u++) {
            int j = 2 * kc + u, c = j * 8 + 2 * tig;
            float2 bb = *(const float2*)(sBias + c);
            float2 w0 = *(const float2*)(sBias + 640 + c);
            float2 w1 = *(const float2*)(sBias + 768 + c);
            float2 w2 = *(const float2*)(sBias + 896 + c);
            float v0 = fsilu(d[j][0] + bb.x + sa0 * w0.x + sa1 * w1.x + sa2 * w2.x);
            float v1 = fsilu(d[j][1] + bb.y + sa0 * w0.y + sa1 * w1.y + sa2 * w2.y);
            float v2 = fsilu(d[j][2] + bb.x + sb0 * w0.x + sb1 * w1.x + sb2 * w2.x);
            float v3 = fsilu(d[j][3] + bb.y + sb0 * w0.y + sb1 * w1.y + sb2 * w2.y);
            ah[kc][2 * u]     = pack2(v0, v1);
            ah[kc][2 * u + 1] = pack2(v2, v3);
        }
}
// L1 epilogue: silu, gate partial, frags, keep m in d
__device__ __forceinline__ void epi_l1(float (&d)[16][4], const float* sBias, int tig,
                                       uint32_t (&ah)[8][4], float& s0, float& s1) {
#pragma unroll
    for (int kc = 0; kc < 8; kc++)
#pragma unroll
        for (int u = 0; u < 2; u++) {
            int j = 2 * kc + u, c = j * 8 + 2 * tig;
            float2 bb = *(const float2*)(sBias + 128 + c);
            float2 wf = *(const float2*)(sBias + 512 + c);
            float v0 = fsilu(d[j][0] + bb.x), v1 = fsilu(d[j][1] + bb.y);
            float v2 = fsilu(d[j][2] + bb.x), v3 = fsilu(d[j][3] + bb.y);
            s0 += v0 * wf.x + v1 * wf.y;
            s1 += v2 * wf.x + v3 * wf.y;
            d[j][0] = v0; d[j][1] = v1; d[j][2] = v2; d[j][3] = v3;
            ah[kc][2 * u]     = pack2(v0, v1);
            ah[kc][2 * u + 1] = pack2(v2, v3);
        }
}
// Lx1 epilogue: phi_x partial dots (3 comps x 2 rows)
__device__ __forceinline__ void epi_lx1(float (&d)[16][4], const float* sBias, int tig,
                                        float* pa, float* pb) {
#pragma unroll
    for (int kc = 0; kc < 8; kc++)
#pragma unroll
        for (int u = 0; u < 2; u++) {
            int j = 2 * kc + u, c = j * 8 + 2 * tig;
            float2 bb = *(const float2*)(sBias + 384 + c);
            float2 q0 = *(const float2*)(sBias + 1024 + c);
            float2 q1 = *(const float2*)(sBias + 1152 + c);
            float2 q2 = *(const float2*)(sBias + 1280 + c);
            float v0 = fsilu(d[j][0] + bb.x), v1 = fsilu(d[j][1] + bb.y);
            float v2 = fsilu(d[j][2] + bb.x), v3 = fsilu(d[j][3] + bb.y);
            pa[0] += v0 * q0.x + v1 * q0.y; pa[1] += v0 * q1.x + v1 * q1.y; pa[2] += v0 * q2.x + v1 * q2.y;
            pb[0] += v2 * q0.x + v3 * q0.y; pb[1] += v2 * q1.x + v3 * q1.y; pb[2] += v2 * q2.x + v3 * q2.y;
        }
}

// ==== edge kernel: 128 edges / 4 warps (M=32 per warp), 2 blocks per SM ====
extern "C" __global__ void __launch_bounds__(128, 2)
edge_kernel(const float* __restrict__ pos, const float* __restrict__ feat,
            const int* __restrict__ senders, const int* __restrict__ receivers,
            const float* __restrict__ b_e0, const float* __restrict__ b_e1,
            const float* __restrict__ b_x0, const float* __restrict__ b_x1,
            const float* __restrict__ b_xo, const float* __restrict__ w_inf,
            const float* __restrict__ b_inf)
{
    extern __shared__ __align__(16) float sm[];
    const uint32_t sA = smem_u32(sm);
    const int tid = threadIdx.x, lane = tid & 31, warp = tid >> 5;
    const int g = lane >> 2, tig = lane & 3;
    const int rA0 = warp * 32 + g, rA1 = rA0 + 8;   // group A rows
    const int rB0 = rA0 + 16,      rB1 = rA0 + 24;  // group B rows
    const int eBase = blockIdx.x * 128;
    const uint32_t* B0 = (const uint32_t*)sm;
    const uint32_t* B1 = B0 + 8192;
    const uint32_t a0 = sA, a1 = sA + 32768;
    float* sBias = sm + EF_BIAS;
    float* sVec  = sm + EF_VEC;
    int*   sRecv = (int*)(sm + EF_RECV);

    loadW32(a0, g_WF[0], tid);           // T0 = L0a.hi
    loadW32(a1, g_WF[1], tid);           // T1 = L0b.hi

    for (int i = tid; i < 128; i += 128) {
        sBias[i] = b_e0[i]; sBias[128 + i] = b_e1[i];
        sBias[256 + i] = b_x0[i]; sBias[384 + i] = b_x1[i];
        sBias[512 + i] = w_inf[i];
    }
    for (int i = tid; i < 384; i += 128) { sBias[640 + i] = g_W0c[i]; sBias[1024 + i] = g_Wout[i]; }
    if (tid < 3) sBias[1408 + tid] = b_xo[tid];
    if (tid == 3) sBias[1411] = b_inf[0];

    {                                    // per-edge geometry (1 edge per thread)
        const int e = eBase + tid;
        const int s = senders[e], rc = receivers[e];
        sRecv[tid] = rc;
        const float* ps = pos + (size_t)s * 9;
        const float* pr = pos + (size_t)rc * 9;
        float* sv = sVec + tid * 16;
#pragma unroll
        for (int v = 0; v < 3; v++) {
            float n2 = 0.f;
#pragma unroll
            for (int dd = 0; dd < 3; dd++) {
                float dv = pr[v * 3 + dd] - ps[v * 3 + dd];
                sv[v * 3 + dd] = dv; n2 += dv * dv;
            }
            sv[9 + v] = (n2 > 0.f) ? sqrtf(n2) : 0.f;
            sv[12 + v] = n2;
        }
    }

    float dA[16][4], dB[16][4];
    uint32_t ahA[8][4], ahB[8][4];

    {   // featS A-frags (4 edges per thread)
        const float* fA0 = feat + (size_t)senders[eBase + rA0] * 128;
        const float* fA1 = feat + (size_t)senders[eBase + rA1] * 128;
        const float* fB0 = feat + (size_t)senders[eBase + rB0] * 128;
        const float* fB1 = feat + (size_t)senders[eBase + rB1] * 128;
#pragma unroll
        for (int kc = 0; kc < 8; kc++) {
            gfrag1(fA0, fA1, kc, tig, ahA);
            gfrag1(fB0, fB1, kc, tig, ahB);
        }
    }
    waitW1(); __syncthreads();           // T0 ready (T1 may be in flight)

    // ---- L0a (featS x W0[0:128]) on b0 ----
    zero_d(dA); zero_d(dB);
    mma2g(dA, dB, ahA, ahB, B0, lane);
    __syncthreads();
    loadW32(a0, g_WF[2], tid);           // T2 = L1.hi -> b0
    {   // featR A-frags
        const float* fA0 = feat + (size_t)receivers[eBase + rA0] * 128;
        const float* fA1 = feat + (size_t)receivers[eBase + rA1] * 128;
        const float* fB0 = feat + (size_t)receivers[eBase + rB0] * 128;
        const float* fB1 = feat + (size_t)receivers[eBase + rB1] * 128;
#pragma unroll
        for (int kc = 0; kc < 8; kc++) {
            gfrag1(fA0, fA1, kc, tig, ahA);
            gfrag1(fB0, fB1, kc, tig, ahB);
        }
    }
    waitW1(); __syncthreads();           // T1 ready (T2 in flight)

    // ---- L0b (featR, accumulate) on b1 ----
    mma2g(dA, dB, ahA, ahB, B1, lane);
    __syncthreads();
    loadW32(a1, g_WF[3], tid);           // T3 = Lx0.hi -> b1
    {   // L0 epilogue
        const float* vA0 = sVec + rA0 * 16; const float* vA1 = sVec + rA1 * 16;
        const float* vB0 = sVec + rB0 * 16; const float* vB1 = sVec + rB1 * 16;
        epi_l0(dA, sBias, tig, vA0[12], vA0[13], vA0[14], vA1[12], vA1[13], vA1[14], ahA);
        epi_l0(dB, sBias, tig, vB0[12], vB0[13], vB0[14], vB1[12], vB1[13], vB1[14], ahB);
    }
    waitW1(); __syncthreads();           // T2 ready (T3 in flight)

    // ---- L1 -> m_ij on b0 ----
    zero_d(dA); zero_d(dB);
    mma2g(dA, dB, ahA, ahB, B0, lane);
    __syncthreads();
    loadW32(a0, g_WF[4], tid);           // T4 = Lx1.hi -> b0
    {   // L1 epilogue: silu, gate, frags, m-scatter
        float sA0 = 0.f, sA1 = 0.f, sB0 = 0.f, sB1 = 0.f;
        epi_l1(dA, sBias, tig, ahA, sA0, sA1);
        epi_l1(dB, sBias, tig, ahB, sB0, sB1);
#pragma unroll
        for (int msk = 1; msk <= 2; msk <<= 1) {
            sA0 += __shfl_xor_sync(0xffffffffu, sA0, msk);
            sA1 += __shfl_xor_sync(0xffffffffu, sA1, msk);
            sB0 += __shfl_xor_sync(0xffffffffu, sB0, msk);
            sB1 += __shfl_xor_sync(0xffffffffu, sB1, msk);
        }
        const float bi = sBias[1411];
        const float gA0 = fsigmoid(sA0 + bi), gA1 = fsigmoid(sA1 + bi);
        const float gB0 = fsigmoid(sB0 + bi), gB1 = fsigmoid(sB1 + bi);
        float* pA0 = g_mAcc + (size_t)sRecv[rA0] * 128;
        float* pA1 = g_mAcc + (size_t)sRecv[rA1] * 128;
        float* pB0 = g_mAcc + (size_t)sRecv[rB0] * 128;
        float* pB1 = g_mAcc + (size_t)sRecv[rB1] * 128;
#pragma unroll
        for (int j = 0; j < 16; j++) {
            int c = j * 8 + 2 * tig;
            red2(pA0 + c, dA[j][0] * gA0, dA[j][1] * gA0);
            red2(pA1 + c, dA[j][2] * gA1, dA[j][3] * gA1);
            red2(pB0 + c, dB[j][0] * gB0, dB[j][1] * gB0);
            red2(pB1 + c, dB[j][2] * gB1, dB[j][3] * gB1);
        }
    }
    waitW1(); __syncthreads();           // T3 ready (T4 in flight)

    // ---- Lx0 on b1 ----
    zero_d(dA); zero_d(dB);
    mma2g(dA, dB, ahA, ahB, B1, lane);
    epi_silu(dA, sBias + 256, tig, ahA);
    epi_silu(dB, sBias + 256, tig, ahB);
    waitW0(); __syncthreads();           // T4 ready

    // ---- Lx1 on b0 ----
    zero_d(dA); zero_d(dB);
    mma2g(dA, dB, ahA, ahB, B0, lane);
    {   // Lx1 epilogue: phi_x dots + shift scatter
        float pA[3] = {0.f, 0.f, 0.f}, pa1[3] = {0.f, 0.f, 0.f};
        float pB[3] = {0.f, 0.f, 0.f}, pb1[3] = {0.f, 0.f, 0.f};
        epi_lx1(dA, sBias, tig, pA, pa1);
        epi_lx1(dB, sBias, tig, pB, pb1);
#pragma unroll
        for (int msk = 1; msk <= 2; msk <<= 1)
#pragma unroll
            for (int v = 0; v < 3; v++) {
                pA[v]  += __shfl_xor_sync(0xffffffffu, pA[v], msk);
                pa1[v] += __shfl_xor_sync(0xffffffffu, pa1[v], msk);
                pB[v]  += __shfl_xor_sync(0xffffffffu, pB[v], msk);
                pb1[v] += __shfl_xor_sync(0xffffffffu, pb1[v], msk);
            }
        if (tig == 0) {
            const int rows[4] = { rA0, rA1, rB0, rB1 };
            const float* pv[4] = { pA, pa1, pB, pb1 };
#pragma unroll
            for (int q = 0; q < 4; q++) {
                const float* sv = sVec + rows[q] * 16;
                float* dst = g_vAcc + (size_t)sRecv[rows[q]] * 9;
#pragma unroll
                for (int v = 0; v < 3; v++) {
                    float sc = (pv[q][v] + sBias[1408 + v]) * frcp(1.0f + sv[9 + v]);
#pragma unroll
                    for (int dd = 0; dd < 3; dd++)
                        atomicAdd(dst + v * 3 + dd, sc * sv[v * 3 + dd]);
                }
            }
        }
    }
}

// ======== node kernel: 64 nodes / 4 warps, full 3-pass, 2 blocks per SM ========
extern "C" __global__ void __launch_bounds__(128, 2)
node_kernel(const float* __restrict__ pos, const float* __restrict__ feat,
            const float* __restrict__ b_h0, const float* __restrict__ b_h1,
            const float* __restrict__ b_h2, float* __restrict__ out)
{
    extern __shared__ __align__(16) float sm[];
    const uint32_t sA = smem_u32(sm);
    const int tid = threadIdx.x, lane = tid & 31, warp = tid >> 5;
    const int g = lane >> 2, tig = lane & 3;
    const int r0 = warp * 16 + g, r1 = r0 + 8;
    const int nBase = blockIdx.x * 64;
    const int node0 = nBase + r0, node1 = nBase + r1;
    const bool va = node0 < N_NODES, vb = node1 < N_NODES;
    const uint32_t* B0 = (const uint32_t*)sm;
    const uint32_t* B1 = B0 + 8192;
    const uint32_t* B2 = B0 + 16384;
    const uint32_t a0 = sA, a1 = sA + 32768, a2 = sA + 65536;
    float* sBias = sm + NF_BIAS;

    loadW32(a0, g_WF[5], tid);           // T5.hi
    loadW32(a1, g_WF[5] + 8192, tid);    // T5.lo
    loadW32(a2, g_WF[6], tid);           // T6.hi
    for (int i = tid; i < 128; i += 128) {
        sBias[i] = b_h0[i]; sBias[128 + i] = b_h1[i]; sBias[256 + i] = b_h2[i];
    }
    const float invNN = 1.0f / 19999.0f;
    for (int idx = tid; idx < 64 * 9; idx += 128) {
        const int i = idx / 9, c = idx - i * 9;
        const int n = nBase + i;
        if (n < N_NODES)
            out[(size_t)n * 9 + c] = pos[(size_t)n * 9 + c] + g_vAcc[(size_t)n * 9 + c] * invNN;
    }

    float d[16][4];
    uint32_t ah[8][4], al[8][4];
    const float invSq = rsqrtf(19999.0f);
    {   // m_i * invSq frags
        const float* f0 = g_mAcc + (size_t)(va ? node0 : 0) * 128;
        const float* f1 = g_mAcc + (size_t)(vb ? node1 : 0) * 128;
#pragma unroll
        for (int kc = 0; kc < 8; kc++) gfrag(f0, f1, kc, tig, ah, al, va, vb, invSq);
    }
    waitW1(); __syncthreads();

    // ---- T5 = H0a (m_i), rotation (0,1,2) ----
    zero_d(d);
    mma12(d, ah, al, B0, lane);
    __syncthreads();
    loadW32(a0, g_WF[6] + 8192, tid);    // T6.lo -> b0
    mma3(d, ah, B1, lane);
    {   // feat frags
        const float* f0 = feat + (size_t)(va ? node0 : 0) * 128;
        const float* f1 = feat + (size_t)(vb ? node1 : 0) * 128;
#pragma unroll
        for (int kc = 0; kc < 8; kc++) gfrag(f0, f1, kc, tig, ah, al, va, vb, 1.f);
    }
    waitW0(); __syncthreads();

    // ---- T6 = H0b (feat, accumulate), rotation (2,0,1) ----
    loadW32(a1, g_WF[7], tid);           // T7.hi -> b1
    mma12(d, ah, al, B2, lane);
    __syncthreads();
    loadW32(a2, g_WF[7] + 8192, tid);    // T7.lo -> b2
    mma3(d, ah, B0, lane);
#pragma unroll
    for (int kc = 0; kc < 8; kc++)        // h0 epilogue
#pragma unroll
        for (int u = 0; u < 2; u++) {
            int j = 2 * kc + u, c = j * 8 + 2 * tig;
            float2 bb = *(const float2*)(sBias + c);
            float v0 = fsilu(d[j][0] + bb.x), v1 = fsilu(d[j][1] + bb.y);
            float v2 = fsilu(d[j][2] + bb.x), v3 = fsilu(d[j][3] + bb.y);
            split2(v0, v1, ah[kc][2 * u], al[kc][2 * u]);
            split2(v2, v3, ah[kc][2 * u + 1], al[kc][2 * u + 1]);
        }
    waitW0(); __syncthreads();

    // ---- T7 = H1, rotation (1,2,0) ----
    loadW32(a0, g_WF[8], tid);           // T8.hi -> b0
    zero_d(d);
    mma12(d, ah, al, B1, lane);
    __syncthreads();
    loadW32(a1, g_WF[8] + 8192, tid);    // T8.lo -> b1
    mma3(d, ah, B2, lane);
#pragma unroll
    for (int kc = 0; kc < 8; kc++)        // h1 epilogue
#pragma unroll
        for (int u = 0; u < 2; u++) {
            int j = 2 * kc + u, c = j * 8 + 2 * tig;
            float2 bb = *(const float2*)(sBias + 128 + c);
            float v0 = fsilu(d[j][0] + bb.x), v1 = fsilu(d[j][1] + bb.y);
            float v2 = fsilu(d[j][2] + bb.x), v3 = fsilu(d[j][3] + bb.y);
            split2(v0, v1, ah[kc][2 * u], al[kc][2 * u]);
            split2(v2, v3, ah[kc][2 * u + 1], al[kc][2 * u + 1]);
        }
    waitW0(); __syncthreads();

    // ---- T8 = H2, rotation (0,1,2) ----
    zero_d(d);
    mma12(d, ah, al, B0, lane);
    mma3(d, ah, B1, lane);
    // h2 + residual -> out
#pragma unroll
    for (int j = 0; j < 16; j++) {
        int c = j * 8 + 2 * tig;
        float2 bb = *(const float2*)(sBias + 256 + c);
        if (va) {
            float2 f = __ldg((const float2*)(feat + (size_t)node0 * 128 + c));
            float2 o = make_float2(d[j][0] + bb.x + f.x, d[j][1] + bb.y + f.y);
            *(float2*)(out + VOFF + (size_t)node0 * 128 + c) = o;
        }
        if (vb) {
            float2 f = __ldg((const float2*)(feat + (size_t)node1 * 128 + c));
            float2 o = make_float2(d[j][2] + bb.x + f.x, d[j][3] + bb.y + f.y);
            *(float2*)(out + VOFF + (size_t)node1 * 128 + c) = o;
        }
    }
}

// ======================= prep + zero =======================
__global__ void prep_kernel(const float* __restrict__ w_e0, const float* __restrict__ w_e1,
                            const float* __restrict__ w_x0, const float* __restrict__ w_x1,
                            const float* __restrict__ w_xo,
                            const float* __restrict__ w_h0, const float* __restrict__ w_h1,
                            const float* __restrict__ w_h2)
{
    const int idx = blockIdx.x * blockDim.x + threadIdx.x;
    const int stride = gridDim.x * blockDim.x;
    const float* srcs[9] = { w_e0, w_e0, w_e1, w_x0, w_x1, w_h0, w_h0, w_h1, w_h2 };
    const int koff[9] = { 0, 128, 0, 0, 0, 0, 128, 0, 0 };
    for (int i = idx; i < 9 * 8192; i += stride) {
        const int t = i >> 13, fi = i & 8191;
        const int ri = fi & 1, ln = (fi >> 1) & 31, j = (fi >> 6) & 15, kc = fi >> 10;
        const int tg = ln & 3, gg = ln >> 2;
        const int k = kc * 16 + ri * 8 + tg * 2;
        const int n = j * 8 + gg;
        const float* s = srcs[t];
        const float wa = s[(size_t)(koff[t] + k) * 128 + n];
        const float wb = s[(size_t)(koff[t] + k + 1) * 128 + n];
        const __half ha = __float2half_rn(wa), hb = __float2half_rn(wb);
        const __half la = __float2half_rn(wa - __half2float(ha));
        const __half lb = __float2half_rn(wb - __half2float(hb));
        g_WF[t][fi] = (uint32_t)__half_as_ushort(ha) | ((uint32_t)__half_as_ushort(hb) << 16);
        g_WF[t][8192 + fi] = (uint32_t)__half_as_ushort(la) | ((uint32_t)__half_as_ushort(lb) << 16);
    }
    for (int i = idx; i < 384; i += stride) {
        const int v = i >> 7, k = i & 127;
        g_W0c[i]  = w_e0[(size_t)(256 + v) * 128 + k];
        g_Wout[i] = w_xo[(size_t)k * 3 + v];
    }
}

__global__ void zero_kernel()
{
    const int idx = blockIdx.x * blockDim.x + threadIdx.x;
    const int stride = gridDim.x * blockDim.x;
    for (int i = idx; i < N_NODES * 128; i += stride) g_mAcc[i] = 0.f;
    for (int i = idx; i < N_NODES * 9; i += stride)   g_vAcc[i] = 0.f;
}

// ======================= launch =======================
extern "C" void kernel_launch(void* const* d_in, const int* in_sizes, int n_in,
                              void* d_out, int out_size)
{
    (void)in_sizes; (void)n_in; (void)out_size;
    const float* pos  = (const float*)d_in[0];
    const float* feat = (const float*)d_in[1];
    const int* senders   = (const int*)d_in[2];
    const int* receivers = (const int*)d_in[3];
    const float* w_e0 = (const float*)d_in[4];  const float* b_e0 = (const float*)d_in[5];
    const float* w_e1 = (const float*)d_in[6];  const float* b_e1 = (const float*)d_in[7];
    const float* w_x0 = (const float*)d_in[8];  const float* b_x0 = (const float*)d_in[9];
    const float* w_x1 = (const float*)d_in[10]; const float* b_x1 = (const float*)d_in[11];
    const float* w_xo = (const float*)d_in[12]; const float* b_xo = (const float*)d_in[13];
    const float* w_if = (const float*)d_in[14]; const float* b_if = (const float*)d_in[15];
    const float* w_h0 = (const float*)d_in[16]; const float* b_h0 = (const float*)d_in[17];
    const float* w_h1 = (const float*)d_in[18]; const float* b_h1 = (const float*)d_in[19];
    const float* w_h2 = (const float*)d_in[20]; const float* b_h2 = (const float*)d_in[21];
    float* out = (float*)d_out;

    cudaFuncSetAttribute(edge_kernel, cudaFuncAttributeMaxDynamicSharedMemorySize, ESM_BYTES);
    cudaFuncSetAttribute(node_kernel, cudaFuncAttributeMaxDynamicSharedMemorySize, NSM_BYTES);

    prep_kernel<<<128, 256>>>(w_e0, w_e1, w_x0, w_x1, w_xo, w_h0, w_h1, w_h2);
    zero_kernel<<<256, 256>>>();
    edge_kernel<<<E_EDGES / 128, 128, ESM_BYTES>>>(pos, feat, senders, receivers,
                                                   b_e0, b_e1, b_x0, b_x1, b_xo, w_if, b_if);
    node_kernel<<<(N_NODES + 63) / 64, 128, NSM_BYTES>>>(pos, feat, b_h0, b_h1, b_h2, out);
}

// round 10
// speedup vs baseline: 1.3463x; 1.3463x over previous
#include <cuda_runtime.h>
#include <cuda_fp16.h>
#include <cstdint>

#define N_NODES 20000
#define E_EDGES 640000
#define VOFF (N_NODES * 9)

// fragment-ordered weight tiles: [tile][hi:0..8191 | lo:8192..16383] u32 (2 fp16 each)
// tiles: 0=L0a 1=L0b 2=L1 3=Lx0 4=Lx1 5=H0a 6=H0b 7=H1 8=H2
__device__ __align__(16) uint32_t g_WF[9][16384];
__device__ float g_W0c[384];    // w_e0 rows 256..258, [v][out]
__device__ float g_Wout[384];   // phi_x_out_w^T [v][k]
__device__ __align__(16) uint32_t g_featH[N_NODES * 64];  // fp16x2 feature table
__device__ __align__(16) float g_mAcc[N_NODES * 128];
__device__ __align__(16) float g_vAcc[N_NODES * 9];

// edge smem (float units): buf0 u32[8192] | buf1 u32[8192] | bias 1536 | vec 1024 | recv 64
#define EF_BIAS 16384
#define EF_VEC  17920
#define EF_RECV 18944
#define ESM_BYTES (19008 * 4)
// node smem: buf0|buf1|buf2 u32[8192 each] | bias 384
#define NF_BIAS 24576
#define NSM_BYTES (24960 * 4)

// ---------------- fast activations (MUFU ex2/rcp) ----------------
__device__ __forceinline__ float fsilu(float x) {
    float e; asm("ex2.approx.f32 %0, %1;" : "=f"(e) : "f"(x * -1.44269504f));
    float r; asm("rcp.approx.f32 %0, %1;" : "=f"(r) : "f"(1.0f + e));
    return x * r;
}
__device__ __forceinline__ float fsigmoid(float x) {
    float e; asm("ex2.approx.f32 %0, %1;" : "=f"(e) : "f"(x * -1.44269504f));
    float r; asm("rcp.approx.f32 %0, %1;" : "=f"(r) : "f"(1.0f + e));
    return r;
}
__device__ __forceinline__ float frcp(float d) {
    float r; asm("rcp.approx.f32 %0, %1;" : "=f"(r) : "f"(d));
    return r;
}

// ---------------- frag / mma helpers ----------------
__device__ __forceinline__ uint32_t smem_u32(const void* p) {
    uint32_t a;
    asm("{ .reg .u64 t; cvta.to.shared.u64 t, %1; cvt.u32.u64 %0, t; }" : "=r"(a) : "l"(p));
    return a;
}
__device__ __forceinline__ uint32_t pack2(float x, float y) {
    __half2 h = __floats2half2_rn(x, y);
    return *reinterpret_cast<uint32_t*>(&h);
}
__device__ __forceinline__ void split2(float x, float y, uint32_t& hi, uint32_t& lo) {
    __half2 h = __floats2half2_rn(x, y);
    float2 hf = __half22float2(h);
    __half2 l = __floats2half2_rn(x - hf.x, y - hf.y);
    hi = *reinterpret_cast<uint32_t*>(&h);
    lo = *reinterpret_cast<uint32_t*>(&l);
}
__device__ __forceinline__ void mma16816(float* d, const uint32_t* a, uint32_t b0, uint32_t b1) {
    asm volatile("mma.sync.aligned.m16n8k16.row.col.f32.f16.f16.f32 "
                 "{%0,%1,%2,%3}, {%4,%5,%6,%7}, {%8,%9}, {%0,%1,%2,%3};"
                 : "+f"(d[0]), "+f"(d[1]), "+f"(d[2]), "+f"(d[3])
                 : "r"(a[0]), "r"(a[1]), "r"(a[2]), "r"(a[3]), "r"(b0), "r"(b1));
}
// single pass (a*Whi) over a 32KB hi buffer — edge kernel
__device__ __forceinline__ void mma1(float (&d)[16][4], const uint32_t (&ah)[8][4],
                                     const uint32_t* swHi, int lane) {
#pragma unroll
    for (int kc = 0; kc < 8; kc++)
#pragma unroll
        for (int j = 0; j < 16; j++) {
            uint2 b = *(const uint2*)&swHi[((kc * 16 + j) * 32 + lane) * 2];
            mma16816(d[j], ah[kc], b.x, b.y);
        }
}
// 2-pass (ah*Whi + al*Whi) — node kernel
__device__ __forceinline__ void mma12(float (&d)[16][4], const uint32_t (&ah)[8][4],
                                      const uint32_t (&al)[8][4], const uint32_t* swHi, int lane) {
#pragma unroll
    for (int kc = 0; kc < 8; kc++)
#pragma unroll
        for (int j = 0; j < 16; j++) {
            uint2 b = *(const uint2*)&swHi[((kc * 16 + j) * 32 + lane) * 2];
            mma16816(d[j], ah[kc], b.x, b.y);
            mma16816(d[j], al[kc], b.x, b.y);
        }
}
// pass 3 (ah*Wlo) — node kernel
__device__ __forceinline__ void mma3(float (&d)[16][4], const uint32_t (&ah)[8][4],
                                     const uint32_t* swLo, int lane) {
#pragma unroll
    for (int kc = 0; kc < 8; kc++)
#pragma unroll
        for (int j = 0; j < 16; j++) {
            uint2 b = *(const uint2*)&swLo[((kc * 16 + j) * 32 + lane) * 2];
            mma16816(d[j], ah[kc], b.x, b.y);
        }
}
__device__ __forceinline__ void zero_d(float (&d)[16][4]) {
#pragma unroll
    for (int j = 0; j < 16; j++)
#pragma unroll
        for (int q = 0; q < 4; q++) d[j][q] = 0.f;
}
// load one 32KB half-tile (2048 x 16B), own commit group
__device__ __forceinline__ void loadW32(uint32_t sAddr, const uint32_t* g, int tid) {
#pragma unroll 1
    for (int i = tid; i < 2048; i += 128)
        asm volatile("cp.async.cg.shared.global [%0], [%1], 16;"
                     :: "r"(sAddr + i * 16), "l"(g + i * 4));
    asm volatile("cp.async.commit_group;" ::: "memory");
}
__device__ __forceinline__ void waitW0() { asm volatile("cp.async.wait_group 0;" ::: "memory"); }
__device__ __forceinline__ void waitW1() { asm volatile("cp.async.wait_group 1;" ::: "memory"); }
__device__ __forceinline__ void red4(float* p, float x, float y, float z, float w) {
    asm volatile("red.global.add.v4.f32 [%0], {%1,%2,%3,%4};"
                 :: "l"(p), "f"(x), "f"(y), "f"(z), "f"(w) : "memory");
}
// gather fp16 frags straight from the pre-converted table
__device__ __forceinline__ void gfragH(const uint32_t* f0, const uint32_t* f1, int tig,
                                       uint32_t (&ah)[8][4]) {
#pragma unroll
    for (int kc = 0; kc < 8; kc++) {
        ah[kc][0] = __ldg(f0 + kc * 8 + tig);
        ah[kc][1] = __ldg(f1 + kc * 8 + tig);
        ah[kc][2] = __ldg(f0 + kc * 8 + 4 + tig);
        ah[kc][3] = __ldg(f1 + kc * 8 + 4 + tig);
    }
}
// hi/lo gather for node kernel (fp32 sources)
__device__ __forceinline__ void gfrag(const float* f0, const float* f1, int kc, int tig,
                                      uint32_t (&ah)[8][4], uint32_t (&al)[8][4],
                                      bool v0, bool v1, float scale) {
    float2 z = make_float2(0.f, 0.f);
    float2 x0 = v0 ? __ldg((const float2*)(f0 + kc * 16 + 2 * tig)) : z;
    float2 x1 = v1 ? __ldg((const float2*)(f1 + kc * 16 + 2 * tig)) : z;
    float2 y0 = v0 ? __ldg((const float2*)(f0 + kc * 16 + 8 + 2 * tig)) : z;
    float2 y1 = v1 ? __ldg((const float2*)(f1 + kc * 16 + 8 + 2 * tig)) : z;
    split2(x0.x * scale, x0.y * scale, ah[kc][0], al[kc][0]);
    split2(x1.x * scale, x1.y * scale, ah[kc][1], al[kc][1]);
    split2(y0.x * scale, y0.y * scale, ah[kc][2], al[kc][2]);
    split2(y1.x * scale, y1.y * scale, ah[kc][3], al[kc][3]);
}

// ======== edge kernel: 64 edges / 4 warps, 1-pass fp16, 3 blocks per SM ========
extern "C" __global__ void __launch_bounds__(128, 3)
edge_kernel(const float* __restrict__ pos, const float* __restrict__ feat,
            const int* __restrict__ senders, const int* __restrict__ receivers,
            const float* __restrict__ b_e0, const float* __restrict__ b_e1,
            const float* __restrict__ b_x0, const float* __restrict__ b_x1,
            const float* __restrict__ b_xo, const float* __restrict__ w_inf,
            const float* __restrict__ b_inf)
{
    extern __shared__ __align__(16) float sm[];
    const uint32_t sA = smem_u32(sm);
    const int tid = threadIdx.x, lane = tid & 31, warp = tid >> 5;
    const int g = lane >> 2, tig = lane & 3;
    const int r0 = warp * 16 + g, r1 = r0 + 8;      // rows 0..63
    const int eBase = blockIdx.x * 64;
    const uint32_t* B0 = (const uint32_t*)sm;
    const uint32_t* B1 = B0 + 8192;
    const uint32_t a0 = sA, a1 = sA + 32768;
    float* sBias = sm + EF_BIAS;
    float* sVec  = sm + EF_VEC;
    int*   sRecv = (int*)(sm + EF_RECV);

    loadW32(a0, g_WF[0], tid);           // T0 = L0a.hi
    loadW32(a1, g_WF[1], tid);           // T1 = L0b.hi

    for (int i = tid; i < 128; i += 128) {
        sBias[i] = b_e0[i]; sBias[128 + i] = b_e1[i];
        sBias[256 + i] = b_x0[i]; sBias[384 + i] = b_x1[i];
        sBias[512 + i] = w_inf[i];
    }
    for (int i = tid; i < 384; i += 128) { sBias[640 + i] = g_W0c[i]; sBias[1024 + i] = g_Wout[i]; }
    if (tid < 3) sBias[1408 + tid] = b_xo[tid];
    if (tid == 3) sBias[1411] = b_inf[0];

    if (tid < 64) {                      // per-edge geometry
        const int e = eBase + tid;
        const int s = senders[e], rc = receivers[e];
        sRecv[tid] = rc;
        const float* ps = pos + (size_t)s * 9;
        const float* pr = pos + (size_t)rc * 9;
        float* sv = sVec + tid * 16;
#pragma unroll
        for (int v = 0; v < 3; v++) {
            float n2 = 0.f;
#pragma unroll
            for (int dd = 0; dd < 3; dd++) {
                float dv = pr[v * 3 + dd] - ps[v * 3 + dd];
                sv[v * 3 + dd] = dv; n2 += dv * dv;
            }
            sv[9 + v] = (n2 > 0.f) ? sqrtf(n2) : 0.f;
            sv[12 + v] = n2;
        }
    }

    float d[16][4];
    uint32_t ah[8][4];
    const int e0 = eBase + r0, e1 = eBase + r1;

    // featS A-frags (pre-converted fp16)
    gfragH(g_featH + (size_t)senders[e0] * 64, g_featH + (size_t)senders[e1] * 64, tig, ah);
    waitW1(); __syncthreads();           // T0 ready (T1 may be in flight)

    // ---- L0a (featS x W0[0:128]) on b0 ----
    zero_d(d);
    mma1(d, ah, B0, lane);
    __syncthreads();
    loadW32(a0, g_WF[2], tid);           // T2 = L1.hi -> b0
    // featR A-frags
    gfragH(g_featH + (size_t)receivers[e0] * 64, g_featH + (size_t)receivers[e1] * 64, tig, ah);
    waitW1(); __syncthreads();           // T1 ready (T2 in flight)

    // ---- L0b (featR, accumulate) on b1 ----
    mma1(d, ah, B1, lane);
    __syncthreads();
    loadW32(a1, g_WF[3], tid);           // T3 = Lx0.hi -> b1
    {   // L0 epilogue: + bias + sq·w0c, silu -> frags
        const float* svr0 = sVec + r0 * 16;
        const float* svr1 = sVec + r1 * 16;
        float sa0 = svr0[12], sa1 = svr0[13], sa2 = svr0[14];
        float sb0 = svr1[12], sb1 = svr1[13], sb2 = svr1[14];
#pragma unroll
        for (int kc = 0; kc < 8; kc++)
#pragma unroll
            for (int u = 0; u < 2; u++) {
                int j = 2 * kc + u, c = j * 8 + 2 * tig;
                float2 bb = *(const float2*)(sBias + c);
                float2 w0 = *(const float2*)(sBias + 640 + c);
                float2 w1 = *(const float2*)(sBias + 768 + c);
                float2 w2 = *(const float2*)(sBias + 896 + c);
                float v0 = fsilu(d[j][0] + bb.x + sa0 * w0.x + sa1 * w1.x + sa2 * w2.x);
                float v1 = fsilu(d[j][1] + bb.y + sa0 * w0.y + sa1 * w1.y + sa2 * w2.y);
                float v2 = fsilu(d[j][2] + bb.x + sb0 * w0.x + sb1 * w1.x + sb2 * w2.x);
                float v3 = fsilu(d[j][3] + bb.y + sb0 * w0.y + sb1 * w1.y + sb2 * w2.y);
                ah[kc][2 * u]     = pack2(v0, v1);
                ah[kc][2 * u + 1] = pack2(v2, v3);
            }
    }
    waitW1(); __syncthreads();           // T2 ready (T3 in flight)

    // ---- L1 -> m_ij on b0 ----
    zero_d(d);
    mma1(d, ah, B0, lane);
    __syncthreads();
    loadW32(a0, g_WF[4], tid);           // T4 = Lx1.hi -> b0
    {   // L1 epilogue: silu, gate dot, frags, v4 m-scatter
        float s0 = 0.f, s1 = 0.f;
#pragma unroll
        for (int kc = 0; kc < 8; kc++)
#pragma unroll
            for (int u = 0; u < 2; u++) {
                int j = 2 * kc + u, c = j * 8 + 2 * tig;
                float2 bb = *(const float2*)(sBias + 128 + c);
                float2 wf = *(const float2*)(sBias + 512 + c);
                float v0 = fsilu(d[j][0] + bb.x), v1 = fsilu(d[j][1] + bb.y);
                float v2 = fsilu(d[j][2] + bb.x), v3 = fsilu(d[j][3] + bb.y);
                s0 += v0 * wf.x + v1 * wf.y;
                s1 += v2 * wf.x + v3 * wf.y;
                d[j][0] = v0; d[j][1] = v1; d[j][2] = v2; d[j][3] = v3;
                ah[kc][2 * u]     = pack2(v0, v1);
                ah[kc][2 * u + 1] = pack2(v2, v3);
            }
        s0 += __shfl_xor_sync(0xffffffffu, s0, 1); s0 += __shfl_xor_sync(0xffffffffu, s0, 2);
        s1 += __shfl_xor_sync(0xffffffffu, s1, 1); s1 += __shfl_xor_sync(0xffffffffu, s1, 2);
        const float bi = sBias[1411];
        const float g0 = fsigmoid(s0 + bi), g1 = fsigmoid(s1 + bi);
        float* p0 = g_mAcc + (size_t)sRecv[r0] * 128;
        float* p1 = g_mAcc + (size_t)sRecv[r1] * 128;
        const bool even = (tig & 1) == 0;
#pragma unroll
        for (int j = 0; j < 16; j++) {
            // pair lanes: even tig emits v4 covering cols [j*8+4*(tig>>1) .. +3]
            float q0 = __shfl_xor_sync(0xffffffffu, d[j][0], 1);
            float q1 = __shfl_xor_sync(0xffffffffu, d[j][1], 1);
            float q2 = __shfl_xor_sync(0xffffffffu, d[j][2], 1);
            float q3 = __shfl_xor_sync(0xffffffffu, d[j][3], 1);
            if (even) {
                int c = j * 8 + 4 * (tig >> 1);
                red4(p0 + c, d[j][0] * g0, d[j][1] * g0, q0 * g0, q1 * g0);
                red4(p1 + c, d[j][2] * g1, d[j][3] * g1, q2 * g1, q3 * g1);
            }
        }
    }
    waitW1(); __syncthreads();           // T3 ready (T4 in flight)

    // ---- Lx0 on b1 ----
    zero_d(d);
    mma1(d, ah, B1, lane);
    {   // Lx0 epilogue
#pragma unroll
        for (int kc = 0; kc < 8; kc++)
#pragma unroll
            for (int u = 0; u < 2; u++) {
                int j = 2 * kc + u, c = j * 8 + 2 * tig;
                float2 bb = *(const float2*)(sBias + 256 + c);
                float v0 = fsilu(d[j][0] + bb.x), v1 = fsilu(d[j][1] + bb.y);
                float v2 = fsilu(d[j][2] + bb.x), v3 = fsilu(d[j][3] + bb.y);
                ah[kc][2 * u]     = pack2(v0, v1);
                ah[kc][2 * u + 1] = pack2(v2, v3);
            }
    }
    waitW0(); __syncthreads();           // T4 ready

    // ---- Lx1 on b0 ----
    zero_d(d);
    mma1(d, ah, B0, lane);
    {   // Lx1 epilogue: phi_x dots + shift scatter
        float pa0 = 0.f, pa1 = 0.f, pa2 = 0.f, pb0 = 0.f, pb1 = 0.f, pb2 = 0.f;
#pragma unroll
        for (int kc = 0; kc < 8; kc++)
#pragma unroll
            for (int u = 0; u < 2; u++) {
                int j = 2 * kc + u, c = j * 8 + 2 * tig;
                float2 bb = *(const float2*)(sBias + 384 + c);
                float2 q0 = *(const float2*)(sBias + 1024 + c);
                float2 q1 = *(const float2*)(sBias + 1152 + c);
                float2 q2 = *(const float2*)(sBias + 1280 + c);
                float v0 = fsilu(d[j][0] + bb.x), v1 = fsilu(d[j][1] + bb.y);
                float v2 = fsilu(d[j][2] + bb.x), v3 = fsilu(d[j][3] + bb.y);
                pa0 += v0 * q0.x + v1 * q0.y; pa1 += v0 * q1.x + v1 * q1.y; pa2 += v0 * q2.x + v1 * q2.y;
                pb0 += v2 * q0.x + v3 * q0.y; pb1 += v2 * q1.x + v3 * q1.y; pb2 += v2 * q2.x + v3 * q2.y;
            }
#pragma unroll
        for (int msk = 1; msk <= 2; msk <<= 1) {
            pa0 += __shfl_xor_sync(0xffffffffu, pa0, msk);
            pa1 += __shfl_xor_sync(0xffffffffu, pa1, msk);
            pa2 += __shfl_xor_sync(0xffffffffu, pa2, msk);
            pb0 += __shfl_xor_sync(0xffffffffu, pb0, msk);
            pb1 += __shfl_xor_sync(0xffffffffu, pb1, msk);
            pb2 += __shfl_xor_sync(0xffffffffu, pb2, msk);
        }
        if (tig == 0) {
            float pv0[3] = { pa0, pa1, pa2 }, pv1[3] = { pb0, pb1, pb2 };
            const float* svr0 = sVec + r0 * 16;
            const float* svr1 = sVec + r1 * 16;
            float* d0 = g_vAcc + (size_t)sRecv[r0] * 9;
            float* d1 = g_vAcc + (size_t)sRecv[r1] * 9;
#pragma unroll
            for (int v = 0; v < 3; v++) {
                float sc0 = (pv0[v] + sBias[1408 + v]) * frcp(1.0f + svr0[9 + v]);
                float sc1 = (pv1[v] + sBias[1408 + v]) * frcp(1.0f + svr1[9 + v]);
#pragma unroll
                for (int dd = 0; dd < 3; dd++) {
                    atomicAdd(d0 + v * 3 + dd, sc0 * svr0[v * 3 + dd]);
                    atomicAdd(d1 + v * 3 + dd, sc1 * svr1[v * 3 + dd]);
                }
            }
        }
    }
}

// ======== node kernel: 64 nodes / 4 warps, full 3-pass, 2 blocks per SM ========
extern "C" __global__ void __launch_bounds__(128, 2)
node_kernel(const float* __restrict__ pos, const float* __restrict__ feat,
            const float* __restrict__ b_h0, const float* __restrict__ b_h1,
            const float* __restrict__ b_h2, float* __restrict__ out)
{
    extern __shared__ __align__(16) float sm[];
    const uint32_t sA = smem_u32(sm);
    const int tid = threadIdx.x, lane = tid & 31, warp = tid >> 5;
    const int g = lane >> 2, tig = lane & 3;
    const int r0 = warp * 16 + g, r1 = r0 + 8;
    const int nBase = blockIdx.x * 64;
    const int node0 = nBase + r0, node1 = nBase + r1;
    const bool va = node0 < N_NODES, vb = node1 < N_NODES;
    const uint32_t* B0 = (const uint32_t*)sm;
    const uint32_t* B1 = B0 + 8192;
    const uint32_t* B2 = B0 + 16384;
    const uint32_t a0 = sA, a1 = sA + 32768, a2 = sA + 65536;
    float* sBias = sm + NF_BIAS;

    loadW32(a0, g_WF[5], tid);           // T5.hi
    loadW32(a1, g_WF[5] + 8192, tid);    // T5.lo
    loadW32(a2, g_WF[6], tid);           // T6.hi
    for (int i = tid; i < 128; i += 128) {
        sBias[i] = b_h0[i]; sBias[128 + i] = b_h1[i]; sBias[256 + i] = b_h2[i];
    }
    const float invNN = 1.0f / 19999.0f;
    for (int idx = tid; idx < 64 * 9; idx += 128) {
        const int i = idx / 9, c = idx - i * 9;
        const int n = nBase + i;
        if (n < N_NODES)
            out[(size_t)n * 9 + c] = pos[(size_t)n * 9 + c] + g_vAcc[(size_t)n * 9 + c] * invNN;
    }

    float d[16][4];
    uint32_t ah[8][4], al[8][4];
    const float invSq = rsqrtf(19999.0f);
    {   // m_i * invSq frags
        const float* f0 = g_mAcc + (size_t)(va ? node0 : 0) * 128;
        const float* f1 = g_mAcc + (size_t)(vb ? node1 : 0) * 128;
#pragma unroll
        for (int kc = 0; kc < 8; kc++) gfrag(f0, f1, kc, tig, ah, al, va, vb, invSq);
    }
    waitW1(); __syncthreads();

    // ---- T5 = H0a (m_i), rotation (0,1,2) ----
    zero_d(d);
    mma12(d, ah, al, B0, lane);
    __syncthreads();
    loadW32(a0, g_WF[6] + 8192, tid);    // T6.lo -> b0
    mma3(d, ah, B1, lane);
    {   // feat frags
        const float* f0 = feat + (size_t)(va ? node0 : 0) * 128;
        const float* f1 = feat + (size_t)(vb ? node1 : 0) * 128;
#pragma unroll
        for (int kc = 0; kc < 8; kc++) gfrag(f0, f1, kc, tig, ah, al, va, vb, 1.f);
    }
    waitW0(); __syncthreads();

    // ---- T6 = H0b (feat, accumulate), rotation (2,0,1) ----
    loadW32(a1, g_WF[7], tid);           // T7.hi -> b1
    mma12(d, ah, al, B2, lane);
    __syncthreads();
    loadW32(a2, g_WF[7] + 8192, tid);    // T7.lo -> b2
    mma3(d, ah, B0, lane);
#pragma unroll
    for (int kc = 0; kc < 8; kc++)        // h0 epilogue
#pragma unroll
        for (int u = 0; u < 2; u++) {
            int j = 2 * kc + u, c = j * 8 + 2 * tig;
            float2 bb = *(const float2*)(sBias + c);
            float v0 = fsilu(d[j][0] + bb.x), v1 = fsilu(d[j][1] + bb.y);
            float v2 = fsilu(d[j][2] + bb.x), v3 = fsilu(d[j][3] + bb.y);
            split2(v0, v1, ah[kc][2 * u], al[kc][2 * u]);
            split2(v2, v3, ah[kc][2 * u + 1], al[kc][2 * u + 1]);
        }
    waitW0(); __syncthreads();

    // ---- T7 = H1, rotation (1,2,0) ----
    loadW32(a0, g_WF[8], tid);           // T8.hi -> b0
    zero_d(d);
    mma12(d, ah, al, B1, lane);
    __syncthreads();
    loadW32(a1, g_WF[8] + 8192, tid);    // T8.lo -> b1
    mma3(d, ah, B2, lane);
#pragma unroll
    for (int kc = 0; kc < 8; kc++)        // h1 epilogue
#pragma unroll
        for (int u = 0; u < 2; u++) {
            int j = 2 * kc + u, c = j * 8 + 2 * tig;
            float2 bb = *(const float2*)(sBias + 128 + c);
            float v0 = fsilu(d[j][0] + bb.x), v1 = fsilu(d[j][1] + bb.y);
            float v2 = fsilu(d[j][2] + bb.x), v3 = fsilu(d[j][3] + bb.y);
            split2(v0, v1, ah[kc][2 * u], al[kc][2 * u]);
            split2(v2, v3, ah[kc][2 * u + 1], al[kc][2 * u + 1]);
        }
    waitW0(); __syncthreads();

    // ---- T8 = H2, rotation (0,1,2) ----
    zero_d(d);
    mma12(d, ah, al, B0, lane);
    mma3(d, ah, B1, lane);
    // h2 + residual -> out
#pragma unroll
    for (int j = 0; j < 16; j++) {
        int c = j * 8 + 2 * tig;
        float2 bb = *(const float2*)(sBias + 256 + c);
        if (va) {
            float2 f = __ldg((const float2*)(feat + (size_t)node0 * 128 + c));
            float2 o = make_float2(d[j][0] + bb.x + f.x, d[j][1] + bb.y + f.y);
            *(float2*)(out + VOFF + (size_t)node0 * 128 + c) = o;
        }
        if (vb) {
            float2 f = __ldg((const float2*)(feat + (size_t)node1 * 128 + c));
            float2 o = make_float2(d[j][2] + bb.x + f.x, d[j][3] + bb.y + f.y);
            *(float2*)(out + VOFF + (size_t)node1 * 128 + c) = o;
        }
    }
}

// ======================= prep + zero =======================
__global__ void prep_kernel(const float* __restrict__ w_e0, const float* __restrict__ w_e1,
                            const float* __restrict__ w_x0, const float* __restrict__ w_x1,
                            const float* __restrict__ w_xo,
                            const float* __restrict__ w_h0, const float* __restrict__ w_h1,
                            const float* __restrict__ w_h2, const float* __restrict__ feat)
{
    const int idx = blockIdx.x * blockDim.x + threadIdx.x;
    const int stride = gridDim.x * blockDim.x;
    const float* srcs[9] = { w_e0, w_e0, w_e1, w_x0, w_x1, w_h0, w_h0, w_h1, w_h2 };
    const int koff[9] = { 0, 128, 0, 0, 0, 0, 128, 0, 0 };
    for (int i = idx; i < 9 * 8192; i += stride) {
        const int t = i >> 13, fi = i & 8191;
        const int ri = fi & 1, ln = (fi >> 1) & 31, j = (fi >> 6) & 15, kc = fi >> 10;
        const int tg = ln & 3, gg = ln >> 2;
        const int k = kc * 16 + ri * 8 + tg * 2;
        const int n = j * 8 + gg;
        const float* s = srcs[t];
        const float wa = s[(size_t)(koff[t] + k) * 128 + n];
        const float wb = s[(size_t)(koff[t] + k + 1) * 128 + n];
        const __half ha = __float2half_rn(wa), hb = __float2half_rn(wb);
        const __half la = __float2half_rn(wa - __half2float(ha));
        const __half lb = __float2half_rn(wb - __half2float(hb));
        g_WF[t][fi] = (uint32_t)__half_as_ushort(ha) | ((uint32_t)__half_as_ushort(hb) << 16);
        g_WF[t][8192 + fi] = (uint32_t)__half_as_ushort(la) | ((uint32_t)__half_as_ushort(lb) << 16);
    }
    for (int i = idx; i < 384; i += stride) {
        const int v = i >> 7, k = i & 127;
        g_W0c[i]  = w_e0[(size_t)(256 + v) * 128 + k];
        g_Wout[i] = w_xo[(size_t)k * 3 + v];
    }
    // fp16 feature table
    for (int i = idx; i < N_NODES * 64; i += stride) {
        float2 f = *(const float2*)(feat + (size_t)i * 2);
        __half2 h = __floats2half2_rn(f.x, f.y);
        g_featH[i] = *reinterpret_cast<uint32_t*>(&h);
    }
}

__global__ void zero_kernel()
{
    const int idx = blockIdx.x * blockDim.x + threadIdx.x;
    const int stride = gridDim.x * blockDim.x;
    for (int i = idx; i < N_NODES * 128; i += stride) g_mAcc[i] = 0.f;
    for (int i = idx; i < N_NODES * 9; i += stride)   g_vAcc[i] = 0.f;
}

// ======================= launch =======================
extern "C" void kernel_launch(void* const* d_in, const int* in_sizes, int n_in,
                              void* d_out, int out_size)
{
    (void)in_sizes; (void)n_in; (void)out_size;
    const float* pos  = (const float*)d_in[0];
    const float* feat = (const float*)d_in[1];
    const int* senders   = (const int*)d_in[2];
    const int* receivers = (const int*)d_in[3];
    const float* w_e0 = (const float*)d_in[4];  const float* b_e0 = (const float*)d_in[5];
    const float* w_e1 = (const float*)d_in[6];  const float* b_e1 = (const float*)d_in[7];
    const float* w_x0 = (const float*)d_in[8];  const float* b_x0 = (const float*)d_in[9];
    const float* w_x1 = (const float*)d_in[10]; const float* b_x1 = (const float*)d_in[11];
    const float* w_xo = (const float*)d_in[12]; const float* b_xo = (const float*)d_in[13];
    const float* w_if = (const float*)d_in[14]; const float* b_if = (const float*)d_in[15];
    const float* w_h0 = (const float*)d_in[16]; const float* b_h0 = (const float*)d_in[17];
    const float* w_h1 = (const float*)d_in[18]; const float* b_h1 = (const float*)d_in[19];
    const float* w_h2 = (const float*)d_in[20]; const float* b_h2 = (const float*)d_in[21];
    float* out = (float*)d_out;

    cudaFuncSetAttribute(edge_kernel, cudaFuncAttributeMaxDynamicSharedMemorySize, ESM_BYTES);
    cudaFuncSetAttribute(node_kernel, cudaFuncAttributeMaxDynamicSharedMemorySize, NSM_BYTES);

    prep_kernel<<<256, 256>>>(w_e0, w_e1, w_x0, w_x1, w_xo, w_h0, w_h1, w_h2, feat);
    zero_kernel<<<256, 256>>>();
    edge_kernel<<<E_EDGES / 64, 128, ESM_BYTES>>>(pos, feat, senders, receivers,
                                                  b_e0, b_e1, b_x0, b_x1, b_xo, w_if, b_if);
    node_kernel<<<(N_NODES + 63) / 64, 128, NSM_BYTES>>>(pos, feat, b_h0, b_h1, b_h2, out);
}

// round 11
// speedup vs baseline: 1.3581x; 1.0088x over previous
#include <cuda_runtime.h>
#include <cuda_fp16.h>
#include <cstdint>

#define N_NODES 20000
#define E_EDGES 640000
#define VOFF (N_NODES * 9)

// fragment-ordered weight tiles: [tile][hi:0..8191 | lo:8192..16383] u32 (2 fp16 each)
// NEW uint4 pair layout: u32 index = ((kc*8 + j/2)*32 + lane)*4 + (j&1)*2 + ri
// tiles: 0=L0a 1=L0b 2=L1 3=Lx0 4=Lx1 5=H0a 6=H0b 7=H1 8=H2
__device__ __align__(16) uint32_t g_WF[9][16384];
__device__ float g_W0c[384];    // w_e0 rows 256..258, [v][out]
__device__ float g_Wout[384];   // phi_x_out_w^T [v][k]
__device__ __align__(16) uint32_t g_featH[N_NODES * 64];  // fp16x2 feature table
__device__ __align__(16) float g_mAcc[N_NODES * 128];
__device__ __align__(16) float g_vAcc[N_NODES * 9];

// edge smem (float units): buf0 u32[8192] | buf1 u32[8192] | bias 1536 | vec 1024 | recv 64
#define EF_BIAS 16384
#define EF_VEC  17920
#define EF_RECV 18944
#define ESM_BYTES (19008 * 4)
// node smem: buf0|buf1|buf2 u32[8192 each] | bias 384
#define NF_BIAS 24576
#define NSM_BYTES (24960 * 4)

// ---------------- fast activations (MUFU ex2/rcp) ----------------
__device__ __forceinline__ float fsilu(float x) {
    float e; asm("ex2.approx.f32 %0, %1;" : "=f"(e) : "f"(x * -1.44269504f));
    float r; asm("rcp.approx.f32 %0, %1;" : "=f"(r) : "f"(1.0f + e));
    return x * r;
}
__device__ __forceinline__ float fsigmoid(float x) {
    float e; asm("ex2.approx.f32 %0, %1;" : "=f"(e) : "f"(x * -1.44269504f));
    float r; asm("rcp.approx.f32 %0, %1;" : "=f"(r) : "f"(1.0f + e));
    return r;
}
__device__ __forceinline__ float frcp(float d) {
    float r; asm("rcp.approx.f32 %0, %1;" : "=f"(r) : "f"(d));
    return r;
}

// ---------------- frag / mma helpers ----------------
__device__ __forceinline__ uint32_t smem_u32(const void* p) {
    uint32_t a;
    asm("{ .reg .u64 t; cvta.to.shared.u64 t, %1; cvt.u32.u64 %0, t; }" : "=r"(a) : "l"(p));
    return a;
}
__device__ __forceinline__ uint32_t pack2(float x, float y) {
    __half2 h = __floats2half2_rn(x, y);
    return *reinterpret_cast<uint32_t*>(&h);
}
__device__ __forceinline__ void split2(float x, float y, uint32_t& hi, uint32_t& lo) {
    __half2 h = __floats2half2_rn(x, y);
    float2 hf = __half22float2(h);
    __half2 l = __floats2half2_rn(x - hf.x, y - hf.y);
    hi = *reinterpret_cast<uint32_t*>(&h);
    lo = *reinterpret_cast<uint32_t*>(&l);
}
__device__ __forceinline__ void mma16816(float* d, const uint32_t* a, uint32_t b0, uint32_t b1) {
    asm volatile("mma.sync.aligned.m16n8k16.row.col.f32.f16.f16.f32 "
                 "{%0,%1,%2,%3}, {%4,%5,%6,%7}, {%8,%9}, {%0,%1,%2,%3};"
                 : "+f"(d[0]), "+f"(d[1]), "+f"(d[2]), "+f"(d[3])
                 : "r"(a[0]), "r"(a[1]), "r"(a[2]), "r"(a[3]), "r"(b0), "r"(b1));
}
// single pass (a*Whi), uint4-paired B loads — edge kernel
__device__ __forceinline__ void mma1(float (&d)[16][4], const uint32_t (&ah)[8][4],
                                     const uint32_t* swHi, int lane) {
#pragma unroll
    for (int kc = 0; kc < 8; kc++)
#pragma unroll
        for (int jp = 0; jp < 8; jp++) {
            uint4 b = *(const uint4*)&swHi[((kc * 8 + jp) * 32 + lane) * 4];
            mma16816(d[2 * jp],     ah[kc], b.x, b.y);
            mma16816(d[2 * jp + 1], ah[kc], b.z, b.w);
        }
}
// 2-pass (ah*Whi + al*Whi), uint4-paired — node kernel
__device__ __forceinline__ void mma12(float (&d)[16][4], const uint32_t (&ah)[8][4],
                                      const uint32_t (&al)[8][4], const uint32_t* swHi, int lane) {
#pragma unroll
    for (int kc = 0; kc < 8; kc++)
#pragma unroll
        for (int jp = 0; jp < 8; jp++) {
            uint4 b = *(const uint4*)&swHi[((kc * 8 + jp) * 32 + lane) * 4];
            mma16816(d[2 * jp],     ah[kc], b.x, b.y);
            mma16816(d[2 * jp],     al[kc], b.x, b.y);
            mma16816(d[2 * jp + 1], ah[kc], b.z, b.w);
            mma16816(d[2 * jp + 1], al[kc], b.z, b.w);
        }
}
// pass 3 (ah*Wlo), uint4-paired — node kernel
__device__ __forceinline__ void mma3(float (&d)[16][4], const uint32_t (&ah)[8][4],
                                     const uint32_t* swLo, int lane) {
#pragma unroll
    for (int kc = 0; kc < 8; kc++)
#pragma unroll
        for (int jp = 0; jp < 8; jp++) {
            uint4 b = *(const uint4*)&swLo[((kc * 8 + jp) * 32 + lane) * 4];
            mma16816(d[2 * jp],     ah[kc], b.x, b.y);
            mma16816(d[2 * jp + 1], ah[kc], b.z, b.w);
        }
}
__device__ __forceinline__ void zero_d(float (&d)[16][4]) {
#pragma unroll
    for (int j = 0; j < 16; j++)
#pragma unroll
        for (int q = 0; q < 4; q++) d[j][q] = 0.f;
}
// load one 32KB half-tile (2048 x 16B), own commit group
__device__ __forceinline__ void loadW32(uint32_t sAddr, const uint32_t* g, int tid) {
#pragma unroll 1
    for (int i = tid; i < 2048; i += 128)
        asm volatile("cp.async.cg.shared.global [%0], [%1], 16;"
                     :: "r"(sAddr + i * 16), "l"(g + i * 4));
    asm volatile("cp.async.commit_group;" ::: "memory");
}
__device__ __forceinline__ void waitW0() { asm volatile("cp.async.wait_group 0;" ::: "memory"); }
__device__ __forceinline__ void waitW1() { asm volatile("cp.async.wait_group 1;" ::: "memory"); }
__device__ __forceinline__ void red4(float* p, float x, float y, float z, float w) {
    asm volatile("red.global.add.v4.f32 [%0], {%1,%2,%3,%4};"
                 :: "l"(p), "f"(x), "f"(y), "f"(z), "f"(w) : "memory");
}
// gather fp16 frags straight from the pre-converted table
__device__ __forceinline__ void gfragH(const uint32_t* f0, const uint32_t* f1, int tig,
                                       uint32_t (&ah)[8][4]) {
#pragma unroll
    for (int kc = 0; kc < 8; kc++) {
        ah[kc][0] = __ldg(f0 + kc * 8 + tig);
        ah[kc][1] = __ldg(f1 + kc * 8 + tig);
        ah[kc][2] = __ldg(f0 + kc * 8 + 4 + tig);
        ah[kc][3] = __ldg(f1 + kc * 8 + 4 + tig);
    }
}
// hi/lo gather for node kernel (fp32 sources)
__device__ __forceinline__ void gfrag(const float* f0, const float* f1, int kc, int tig,
                                      uint32_t (&ah)[8][4], uint32_t (&al)[8][4],
                                      bool v0, bool v1, float scale) {
    float2 z = make_float2(0.f, 0.f);
    float2 x0 = v0 ? __ldg((const float2*)(f0 + kc * 16 + 2 * tig)) : z;
    float2 x1 = v1 ? __ldg((const float2*)(f1 + kc * 16 + 2 * tig)) : z;
    float2 y0 = v0 ? __ldg((const float2*)(f0 + kc * 16 + 8 + 2 * tig)) : z;
    float2 y1 = v1 ? __ldg((const float2*)(f1 + kc * 16 + 8 + 2 * tig)) : z;
    split2(x0.x * scale, x0.y * scale, ah[kc][0], al[kc][0]);
    split2(x1.x * scale, x1.y * scale, ah[kc][1], al[kc][1]);
    split2(y0.x * scale, y0.y * scale, ah[kc][2], al[kc][2]);
    split2(y1.x * scale, y1.y * scale, ah[kc][3], al[kc][3]);
}

// ======== edge kernel: 64 edges / 4 warps, 1-pass fp16, 3 blocks per SM ========
extern "C" __global__ void __launch_bounds__(128, 3)
edge_kernel(const float* __restrict__ pos, const float* __restrict__ feat,
            const int* __restrict__ senders, const int* __restrict__ receivers,
            const float* __restrict__ b_e0, const float* __restrict__ b_e1,
            const float* __restrict__ b_x0, const float* __restrict__ b_x1,
            const float* __restrict__ b_xo, const float* __restrict__ w_inf,
            const float* __restrict__ b_inf)
{
    extern __shared__ __align__(16) float sm[];
    const uint32_t sA = smem_u32(sm);
    const int tid = threadIdx.x, lane = tid & 31, warp = tid >> 5;
    const int g = lane >> 2, tig = lane & 3;
    const int r0 = warp * 16 + g, r1 = r0 + 8;      // rows 0..63
    const int eBase = blockIdx.x * 64;
    const uint32_t* B0 = (const uint32_t*)sm;
    const uint32_t* B1 = B0 + 8192;
    const uint32_t a0 = sA, a1 = sA + 32768;
    float* sBias = sm + EF_BIAS;
    float* sVec  = sm + EF_VEC;
    int*   sRecv = (int*)(sm + EF_RECV);

    loadW32(a0, g_WF[0], tid);           // T0 = L0a.hi
    loadW32(a1, g_WF[1], tid);           // T1 = L0b.hi

    for (int i = tid; i < 128; i += 128) {
        sBias[i] = b_e0[i]; sBias[128 + i] = b_e1[i];
        sBias[256 + i] = b_x0[i]; sBias[384 + i] = b_x1[i];
        sBias[512 + i] = w_inf[i];
    }
    for (int i = tid; i < 384; i += 128) { sBias[640 + i] = g_W0c[i]; sBias[1024 + i] = g_Wout[i]; }
    if (tid < 3) sBias[1408 + tid] = b_xo[tid];
    if (tid == 3) sBias[1411] = b_inf[0];

    if (tid < 64) {                      // per-edge geometry
        const int e = eBase + tid;
        const int s = senders[e], rc = receivers[e];
        sRecv[tid] = rc;
        const float* ps = pos + (size_t)s * 9;
        const float* pr = pos + (size_t)rc * 9;
        float* sv = sVec + tid * 16;
#pragma unroll
        for (int v = 0; v < 3; v++) {
            float n2 = 0.f;
#pragma unroll
            for (int dd = 0; dd < 3; dd++) {
                float dv = pr[v * 3 + dd] - ps[v * 3 + dd];
                sv[v * 3 + dd] = dv; n2 += dv * dv;
            }
            sv[9 + v] = (n2 > 0.f) ? sqrtf(n2) : 0.f;
            sv[12 + v] = n2;
        }
    }

    float d[16][4];
    uint32_t ah[8][4];
    const int e0 = eBase + r0, e1 = eBase + r1;

    // featS A-frags (pre-converted fp16)
    gfragH(g_featH + (size_t)senders[e0] * 64, g_featH + (size_t)senders[e1] * 64, tig, ah);
    waitW1(); __syncthreads();           // T0 ready (T1 may be in flight)

    // ---- L0a (featS x W0[0:128]) on b0 ----
    zero_d(d);
    mma1(d, ah, B0, lane);
    __syncthreads();
    loadW32(a0, g_WF[2], tid);           // T2 = L1.hi -> b0
    // featR A-frags
    gfragH(g_featH + (size_t)receivers[e0] * 64, g_featH + (size_t)receivers[e1] * 64, tig, ah);
    waitW1(); __syncthreads();           // T1 ready (T2 in flight)

    // ---- L0b (featR, accumulate) on b1 ----
    mma1(d, ah, B1, lane);
    __syncthreads();
    loadW32(a1, g_WF[3], tid);           // T3 = Lx0.hi -> b1
    {   // L0 epilogue: + bias + sq·w0c, silu -> frags
        const float* svr0 = sVec + r0 * 16;
        const float* svr1 = sVec + r1 * 16;
        float sa0 = svr0[12], sa1 = svr0[13], sa2 = svr0[14];
        float sb0 = svr1[12], sb1 = svr1[13], sb2 = svr1[14];
#pragma unroll
        for (int kc = 0; kc < 8; kc++)
#pragma unroll
            for (int u = 0; u < 2; u++) {
                int j = 2 * kc + u, c = j * 8 + 2 * tig;
                float2 bb = *(const float2*)(sBias + c);
                float2 w0 = *(const float2*)(sBias + 640 + c);
                float2 w1 = *(const float2*)(sBias + 768 + c);
                float2 w2 = *(const float2*)(sBias + 896 + c);
                float v0 = fsilu(d[j][0] + bb.x + sa0 * w0.x + sa1 * w1.x + sa2 * w2.x);
                float v1 = fsilu(d[j][1] + bb.y + sa0 * w0.y + sa1 * w1.y + sa2 * w2.y);
                float v2 = fsilu(d[j][2] + bb.x + sb0 * w0.x + sb1 * w1.x + sb2 * w2.x);
                float v3 = fsilu(d[j][3] + bb.y + sb0 * w0.y + sb1 * w1.y + sb2 * w2.y);
                ah[kc][2 * u]     = pack2(v0, v1);
                ah[kc][2 * u + 1] = pack2(v2, v3);
            }
    }
    waitW1(); __syncthreads();           // T2 ready (T3 in flight)

    // ---- L1 -> m_ij on b0 ----
    zero_d(d);
    mma1(d, ah, B0, lane);
    __syncthreads();
    loadW32(a0, g_WF[4], tid);           // T4 = Lx1.hi -> b0
    {   // L1 epilogue: silu, gate dot, frags, v4 m-scatter
        float s0 = 0.f, s1 = 0.f;
#pragma unroll
        for (int kc = 0; kc < 8; kc++)
#pragma unroll
            for (int u = 0; u < 2; u++) {
                int j = 2 * kc + u, c = j * 8 + 2 * tig;
                float2 bb = *(const float2*)(sBias + 128 + c);
                float2 wf = *(const float2*)(sBias + 512 + c);
                float v0 = fsilu(d[j][0] + bb.x), v1 = fsilu(d[j][1] + bb.y);
                float v2 = fsilu(d[j][2] + bb.x), v3 = fsilu(d[j][3] + bb.y);
                s0 += v0 * wf.x + v1 * wf.y;
                s1 += v2 * wf.x + v3 * wf.y;
                d[j][0] = v0; d[j][1] = v1; d[j][2] = v2; d[j][3] = v3;
                ah[kc][2 * u]     = pack2(v0, v1);
                ah[kc][2 * u + 1] = pack2(v2, v3);
            }
        s0 += __shfl_xor_sync(0xffffffffu, s0, 1); s0 += __shfl_xor_sync(0xffffffffu, s0, 2);
        s1 += __shfl_xor_sync(0xffffffffu, s1, 1); s1 += __shfl_xor_sync(0xffffffffu, s1, 2);
        const float bi = sBias[1411];
        const float g0 = fsigmoid(s0 + bi), g1 = fsigmoid(s1 + bi);
        float* p0 = g_mAcc + (size_t)sRecv[r0] * 128;
        float* p1 = g_mAcc + (size_t)sRecv[r1] * 128;
        const bool even = (tig & 1) == 0;
#pragma unroll
        for (int j = 0; j < 16; j++) {
            float q0 = __shfl_xor_sync(0xffffffffu, d[j][0], 1);
            float q1 = __shfl_xor_sync(0xffffffffu, d[j][1], 1);
            float q2 = __shfl_xor_sync(0xffffffffu, d[j][2], 1);
            float q3 = __shfl_xor_sync(0xffffffffu, d[j][3], 1);
            if (even) {
                int c = j * 8 + 4 * (tig >> 1);
                red4(p0 + c, d[j][0] * g0, d[j][1] * g0, q0 * g0, q1 * g0);
                red4(p1 + c, d[j][2] * g1, d[j][3] * g1, q2 * g1, q3 * g1);
            }
        }
    }
    waitW1(); __syncthreads();           // T3 ready (T4 in flight)

    // ---- Lx0 on b1 ----
    zero_d(d);
    mma1(d, ah, B1, lane);
    {   // Lx0 epilogue
#pragma unroll
        for (int kc = 0; kc < 8; kc++)
#pragma unroll
            for (int u = 0; u < 2; u++) {
                int j = 2 * kc + u, c = j * 8 + 2 * tig;
                float2 bb = *(const float2*)(sBias + 256 + c);
                float v0 = fsilu(d[j][0] + bb.x), v1 = fsilu(d[j][1] + bb.y);
                float v2 = fsilu(d[j][2] + bb.x), v3 = fsilu(d[j][3] + bb.y);
                ah[kc][2 * u]     = pack2(v0, v1);
                ah[kc][2 * u + 1] = pack2(v2, v3);
            }
    }
    waitW0(); __syncthreads();           // T4 ready

    // ---- Lx1 on b0 ----
    zero_d(d);
    mma1(d, ah, B0, lane);
    {   // Lx1 epilogue: phi_x dots + shift scatter
        float pa0 = 0.f, pa1 = 0.f, pa2 = 0.f, pb0 = 0.f, pb1 = 0.f, pb2 = 0.f;
#pragma unroll
        for (int kc = 0; kc < 8; kc++)
#pragma unroll
            for (int u = 0; u < 2; u++) {
                int j = 2 * kc + u, c = j * 8 + 2 * tig;
                float2 bb = *(const float2*)(sBias + 384 + c);
                float2 q0 = *(const float2*)(sBias + 1024 + c);
                float2 q1 = *(const float2*)(sBias + 1152 + c);
                float2 q2 = *(const float2*)(sBias + 1280 + c);
                float v0 = fsilu(d[j][0] + bb.x), v1 = fsilu(d[j][1] + bb.y);
                float v2 = fsilu(d[j][2] + bb.x), v3 = fsilu(d[j][3] + bb.y);
                pa0 += v0 * q0.x + v1 * q0.y; pa1 += v0 * q1.x + v1 * q1.y; pa2 += v0 * q2.x + v1 * q2.y;
                pb0 += v2 * q0.x + v3 * q0.y; pb1 += v2 * q1.x + v3 * q1.y; pb2 += v2 * q2.x + v3 * q2.y;
            }
#pragma unroll
        for (int msk = 1; msk <= 2; msk <<= 1) {
            pa0 += __shfl_xor_sync(0xffffffffu, pa0, msk);
            pa1 += __shfl_xor_sync(0xffffffffu, pa1, msk);
            pa2 += __shfl_xor_sync(0xffffffffu, pa2, msk);
            pb0 += __shfl_xor_sync(0xffffffffu, pb0, msk);
            pb1 += __shfl_xor_sync(0xffffffffu, pb1, msk);
            pb2 += __shfl_xor_sync(0xffffffffu, pb2, msk);
        }
        if (tig == 0) {
            float pv0[3] = { pa0, pa1, pa2 }, pv1[3] = { pb0, pb1, pb2 };
            const float* svr0 = sVec + r0 * 16;
            const float* svr1 = sVec + r1 * 16;
            float* d0 = g_vAcc + (size_t)sRecv[r0] * 9;
            float* d1 = g_vAcc + (size_t)sRecv[r1] * 9;
#pragma unroll
            for (int v = 0; v < 3; v++) {
                float sc0 = (pv0[v] + sBias[1408 + v]) * frcp(1.0f + svr0[9 + v]);
                float sc1 = (pv1[v] + sBias[1408 + v]) * frcp(1.0f + svr1[9 + v]);
#pragma unroll
                for (int dd = 0; dd < 3; dd++) {
                    atomicAdd(d0 + v * 3 + dd, sc0 * svr0[v * 3 + dd]);
                    atomicAdd(d1 + v * 3 + dd, sc1 * svr1[v * 3 + dd]);
                }
            }
        }
    }
}

// ======== node kernel: 64 nodes / 4 warps, full 3-pass, 2 blocks per SM ========
extern "C" __global__ void __launch_bounds__(128, 2)
node_kernel(const float* __restrict__ pos, const float* __restrict__ feat,
            const float* __restrict__ b_h0, const float* __restrict__ b_h1,
            const float* __restrict__ b_h2, float* __restrict__ out)
{
    extern __shared__ __align__(16) float sm[];
    const uint32_t sA = smem_u32(sm);
    const int tid = threadIdx.x, lane = tid & 31, warp = tid >> 5;
    const int g = lane >> 2, tig = lane & 3;
    const int r0 = warp * 16 + g, r1 = r0 + 8;
    const int nBase = blockIdx.x * 64;
    const int node0 = nBase + r0, node1 = nBase + r1;
    const bool va = node0 < N_NODES, vb = node1 < N_NODES;
    const uint32_t* B0 = (const uint32_t*)sm;
    const uint32_t* B1 = B0 + 8192;
    const uint32_t* B2 = B0 + 16384;
    const uint32_t a0 = sA, a1 = sA + 32768, a2 = sA + 65536;
    float* sBias = sm + NF_BIAS;

    loadW32(a0, g_WF[5], tid);           // T5.hi
    loadW32(a1, g_WF[5] + 8192, tid);    // T5.lo
    loadW32(a2, g_WF[6], tid);           // T6.hi
    for (int i = tid; i < 128; i += 128) {
        sBias[i] = b_h0[i]; sBias[128 + i] = b_h1[i]; sBias[256 + i] = b_h2[i];
    }
    const float invNN = 1.0f / 19999.0f;
    for (int idx = tid; idx < 64 * 9; idx += 128) {
        const int i = idx / 9, c = idx - i * 9;
        const int n = nBase + i;
        if (n < N_NODES)
            out[(size_t)n * 9 + c] = pos[(size_t)n * 9 + c] + g_vAcc[(size_t)n * 9 + c] * invNN;
    }

    float d[16][4];
    uint32_t ah[8][4], al[8][4];
    const float invSq = rsqrtf(19999.0f);
    {   // m_i * invSq frags
        const float* f0 = g_mAcc + (size_t)(va ? node0 : 0) * 128;
        const float* f1 = g_mAcc + (size_t)(vb ? node1 : 0) * 128;
#pragma unroll
        for (int kc = 0; kc < 8; kc++) gfrag(f0, f1, kc, tig, ah, al, va, vb, invSq);
    }
    waitW1(); __syncthreads();

    // ---- T5 = H0a (m_i), rotation (0,1,2) ----
    zero_d(d);
    mma12(d, ah, al, B0, lane);
    __syncthreads();
    loadW32(a0, g_WF[6] + 8192, tid);    // T6.lo -> b0
    mma3(d, ah, B1, lane);
    {   // feat frags
        const float* f0 = feat + (size_t)(va ? node0 : 0) * 128;
        const float* f1 = feat + (size_t)(vb ? node1 : 0) * 128;
#pragma unroll
        for (int kc = 0; kc < 8; kc++) gfrag(f0, f1, kc, tig, ah, al, va, vb, 1.f);
    }
    waitW0(); __syncthreads();

    // ---- T6 = H0b (feat, accumulate), rotation (2,0,1) ----
    loadW32(a1, g_WF[7], tid);           // T7.hi -> b1
    mma12(d, ah, al, B2, lane);
    __syncthreads();
    loadW32(a2, g_WF[7] + 8192, tid);    // T7.lo -> b2
    mma3(d, ah, B0, lane);
#pragma unroll
    for (int kc = 0; kc < 8; kc++)        // h0 epilogue
#pragma unroll
        for (int u = 0; u < 2; u++) {
            int j = 2 * kc + u, c = j * 8 + 2 * tig;
            float2 bb = *(const float2*)(sBias + c);
            float v0 = fsilu(d[j][0] + bb.x), v1 = fsilu(d[j][1] + bb.y);
            float v2 = fsilu(d[j][2] + bb.x), v3 = fsilu(d[j][3] + bb.y);
            split2(v0, v1, ah[kc][2 * u], al[kc][2 * u]);
            split2(v2, v3, ah[kc][2 * u + 1], al[kc][2 * u + 1]);
        }
    waitW0(); __syncthreads();

    // ---- T7 = H1, rotation (1,2,0) ----
    loadW32(a0, g_WF[8], tid);           // T8.hi -> b0
    zero_d(d);
    mma12(d, ah, al, B1, lane);
    __syncthreads();
    loadW32(a1, g_WF[8] + 8192, tid);    // T8.lo -> b1
    mma3(d, ah, B2, lane);
#pragma unroll
    for (int kc = 0; kc < 8; kc++)        // h1 epilogue
#pragma unroll
        for (int u = 0; u < 2; u++) {
            int j = 2 * kc + u, c = j * 8 + 2 * tig;
            float2 bb = *(const float2*)(sBias + 128 + c);
            float v0 = fsilu(d[j][0] + bb.x), v1 = fsilu(d[j][1] + bb.y);
            float v2 = fsilu(d[j][2] + bb.x), v3 = fsilu(d[j][3] + bb.y);
            split2(v0, v1, ah[kc][2 * u], al[kc][2 * u]);
            split2(v2, v3, ah[kc][2 * u + 1], al[kc][2 * u + 1]);
        }
    waitW0(); __syncthreads();

    // ---- T8 = H2, rotation (0,1,2) ----
    zero_d(d);
    mma12(d, ah, al, B0, lane);
    mma3(d, ah, B1, lane);
    // h2 + residual -> out
#pragma unroll
    for (int j = 0; j < 16; j++) {
        int c = j * 8 + 2 * tig;
        float2 bb = *(const float2*)(sBias + 256 + c);
        if (va) {
            float2 f = __ldg((const float2*)(feat + (size_t)node0 * 128 + c));
            float2 o = make_float2(d[j][0] + bb.x + f.x, d[j][1] + bb.y + f.y);
            *(float2*)(out + VOFF + (size_t)node0 * 128 + c) = o;
        }
        if (vb) {
            float2 f = __ldg((const float2*)(feat + (size_t)node1 * 128 + c));
            float2 o = make_float2(d[j][2] + bb.x + f.x, d[j][3] + bb.y + f.y);
            *(float2*)(out + VOFF + (size_t)node1 * 128 + c) = o;
        }
    }
}

// ======================= prep + zero =======================
__global__ void prep_kernel(const float* __restrict__ w_e0, const float* __restrict__ w_e1,
                            const float* __restrict__ w_x0, const float* __restrict__ w_x1,
                            const float* __restrict__ w_xo,
                            const float* __restrict__ w_h0, const float* __restrict__ w_h1,
                            const float* __restrict__ w_h2, const float* __restrict__ feat)
{
    const int idx = blockIdx.x * blockDim.x + threadIdx.x;
    const int stride = gridDim.x * blockDim.x;
    const float* srcs[9] = { w_e0, w_e0, w_e1, w_x0, w_x1, w_h0, w_h0, w_h1, w_h2 };
    const int koff[9] = { 0, 128, 0, 0, 0, 0, 128, 0, 0 };
    for (int i = idx; i < 9 * 8192; i += stride) {
        const int t = i >> 13, fi = i & 8191;
        // uint4 pair layout: fi = ((kc*8 + jp)*32 + lane)*4 + jlo*2 + ri
        const int q = fi & 3, ri = q & 1, jlo = q >> 1;
        const int ln = (fi >> 2) & 31;
        const int jp = (fi >> 7) & 7;
        const int kc = fi >> 10;
        const int j = jp * 2 + jlo;
        const int tg = ln & 3, gg = ln >> 2;
        const int k = kc * 16 + ri * 8 + tg * 2;
        const int n = j * 8 + gg;
        const float* s = srcs[t];
        const float wa = s[(size_t)(koff[t] + k) * 128 + n];
        const float wb = s[(size_t)(koff[t] + k + 1) * 128 + n];
        const __half ha = __float2half_rn(wa), hb = __float2half_rn(wb);
        const __half la = __float2half_rn(wa - __half2float(ha));
        const __half lb = __float2half_rn(wb - __half2float(hb));
        g_WF[t][fi] = (uint32_t)__half_as_ushort(ha) | ((uint32_t)__half_as_ushort(hb) << 16);
        g_WF[t][8192 + fi] = (uint32_t)__half_as_ushort(la) | ((uint32_t)__half_as_ushort(lb) << 16);
    }
    for (int i = idx; i < 384; i += stride) {
        const int v = i >> 7, k = i & 127;
        g_W0c[i]  = w_e0[(size_t)(256 + v) * 128 + k];
        g_Wout[i] = w_xo[(size_t)k * 3 + v];
    }
    // fp16 feature table
    for (int i = idx; i < N_NODES * 64; i += stride) {
        float2 f = *(const float2*)(feat + (size_t)i * 2);
        __half2 h = __floats2half2_rn(f.x, f.y);
        g_featH[i] = *reinterpret_cast<uint32_t*>(&h);
    }
}

__global__ void zero_kernel()
{
    const int idx = blockIdx.x * blockDim.x + threadIdx.x;
    const int stride = gridDim.x * blockDim.x;
    for (int i = idx; i < N_NODES * 128; i += stride) g_mAcc[i] = 0.f;
    for (int i = idx; i < N_NODES * 9; i += stride)   g_vAcc[i] = 0.f;
}

// ======================= launch =======================
extern "C" void kernel_launch(void* const* d_in, const int* in_sizes, int n_in,
                              void* d_out, int out_size)
{
    (void)in_sizes; (void)n_in; (void)out_size;
    const float* pos  = (const float*)d_in[0];
    const float* feat = (const float*)d_in[1];
    const int* senders   = (const int*)d_in[2];
    const int* receivers = (const int*)d_in[3];
    const float* w_e0 = (const float*)d_in[4];  const float* b_e0 = (const float*)d_in[5];
    const float* w_e1 = (const float*)d_in[6];  const float* b_e1 = (const float*)d_in[7];
    const float* w_x0 = (const float*)d_in[8];  const float* b_x0 = (const float*)d_in[9];
    const float* w_x1 = (const float*)d_in[10]; const float* b_x1 = (const float*)d_in[11];
    const float* w_xo = (const float*)d_in[12]; const float* b_xo = (const float*)d_in[13];
    const float* w_if = (const float*)d_in[14]; const float* b_if = (const float*)d_in[15];
    const float* w_h0 = (const float*)d_in[16]; const float* b_h0 = (const float*)d_in[17];
    const float* w_h1 = (const float*)d_in[18]; const float* b_h1 = (const float*)d_in[19];
    const float* w_h2 = (const float*)d_in[20]; const float* b_h2 = (const float*)d_in[21];
    float* out = (float*)d_out;

    cudaFuncSetAttribute(edge_kernel, cudaFuncAttributeMaxDynamicSharedMemorySize, ESM_BYTES);
    cudaFuncSetAttribute(node_kernel, cudaFuncAttributeMaxDynamicSharedMemorySize, NSM_BYTES);

    prep_kernel<<<256, 256>>>(w_e0, w_e1, w_x0, w_x1, w_xo, w_h0, w_h1, w_h2, feat);
    zero_kernel<<<256, 256>>>();
    edge_kernel<<<E_EDGES / 64, 128, ESM_BYTES>>>(pos, feat, senders, receivers,
                                                  b_e0, b_e1, b_x0, b_x1, b_xo, w_if, b_if);
    node_kernel<<<(N_NODES + 63) / 64, 128, NSM_BYTES>>>(pos, feat, b_h0, b_h1, b_h2, out);
}